// round 6
// baseline (speedup 1.0000x reference)
#include <cuda_runtime.h>
#include <cstdint>

#define DM   1024
#define SEQ  2048
#define BATCH 4
#define NH   16
#define DH   64

// Scratch (allocation-free)
__device__ float g_Q[BATCH * NH * SEQ * DH];   // [B,H,S,Dh], pre-scaled by Dh^-0.5
__device__ float g_K[BATCH * NH * SEQ * DH];
__device__ float g_V[BATCH * NH * SEQ * DH];
__device__ float g_O[BATCH * SEQ * DM];        // [B,S,D]

// ============================================================================
// Helpers
// ============================================================================
__device__ __forceinline__ uint32_t f2tf32(float x) {
    uint32_t u;
    asm("cvt.rna.tf32.f32 %0, %1;" : "=r"(u) : "f"(x));
    return u;
}
__device__ __forceinline__ uint32_t smem_u32(const void* p) {
    uint32_t a;
    asm("{ .reg .u64 t; cvta.to.shared.u64 t, %1; cvt.u32.u64 %0, t; }" : "=r"(a) : "l"(p));
    return a;
}

#define MMA_TF32(d, a, b0v, b1v)                                               \
    asm volatile("mma.sync.aligned.m16n8k8.row.col.f32.tf32.tf32.f32 "         \
                 "{%0,%1,%2,%3}, {%4,%5,%6,%7}, {%8,%9}, {%0,%1,%2,%3};"       \
                 : "+f"((d)[0]), "+f"((d)[1]), "+f"((d)[2]), "+f"((d)[3])      \
                 : "r"((a)[0]), "r"((a)[1]), "r"((a)[2]), "r"((a)[3]),         \
                   "r"(b0v), "r"(b1v))

#define LDSM_X4(d, addr)                                                       \
    asm volatile("ldmatrix.sync.aligned.m8n8.x4.shared.b16 {%0,%1,%2,%3}, [%4];" \
                 : "=r"((d)[0]), "=r"((d)[1]), "=r"((d)[2]), "=r"((d)[3])      \
                 : "r"(addr))

#define CP_ASYNC16(saddr, gptr)                                                \
    asm volatile("cp.async.cg.shared.global [%0], [%1], 16;"                   \
                 :: "r"(saddr), "l"(gptr))
#define CP_COMMIT() asm volatile("cp.async.commit_group;" ::: "memory")
#define CP_WAIT2()  asm volatile("cp.async.wait_group 2;" ::: "memory")

#define SST 20
#define STAGE_WORDS (2 * 2560)               // A tile + W tile per stage
#define STAGE_BYTES (STAGE_WORDS * 4)
#define GEMM_SMEM_BYTES (4 * STAGE_BYTES)    // 4 stages = 80 KB

// ============================================================================
// GEMM mainloop: CTA 128x128, 4 warps, warp tile 64x64, cp.async 4-stage.
// smem holds raw fp32; fragments converted to tf32 post-ldmatrix.
// ============================================================================
__device__ __forceinline__ void gemm_mainloop_cp(const float* __restrict__ Ablk,
                                                 const float* __restrict__ Wblk,
                                                 uint32_t* smg,
                                                 float (*acc)[8][4],
                                                 int tid) {
    const int lane = tid & 31;
    const int wid = tid >> 5;
    const int wm = (wid & 1) << 6;
    const int wn = (wid >> 1) << 6;
    const int mat = lane >> 3, lrow = lane & 7;
    const int a_row = wm + ((mat & 1) << 3) + lrow;
    const int a_col = (mat >> 1) << 2;
    const int b_row = wn + ((mat >> 1) << 3) + lrow;
    const int b_col = (mat & 1) << 2;
    const uint32_t smb = smem_u32(smg);

    const int ld_r = tid >> 2;        // 0..31 (+32*it)
    const int ld_f = (tid & 3) << 2;  // word offset 0,4,8,12

#pragma unroll
    for (int mt = 0; mt < 4; mt++)
#pragma unroll
        for (int nt = 0; nt < 8; nt++)
#pragma unroll
            for (int e = 0; e < 4; e++) acc[mt][nt][e] = 0.0f;

    // prologue: issue stages 0..2
#pragma unroll
    for (int s = 0; s < 3; s++) {
        const uint32_t dst = smb + (uint32_t)s * STAGE_BYTES;
        const float* a = Ablk + s * 16;
        const float* w = Wblk + s * 16;
#pragma unroll
        for (int it = 0; it < 4; it++) {
            const int row = it * 32 + ld_r;
            const uint32_t so = dst + (uint32_t)((row * SST + ld_f) * 4);
            CP_ASYNC16(so, a + (size_t)row * DM + ld_f);
            CP_ASYNC16(so + 2560 * 4, w + (size_t)row * DM + ld_f);
        }
        CP_COMMIT();
    }

#pragma unroll 1
    for (int c = 0; c < 64; c++) {
        CP_WAIT2();
        __syncthreads();
        // issue stage c+3 (overwrites the buffer consumed at iter c-1)
        if (c + 3 < 64) {
            const int s = (c + 3) & 3;
            const uint32_t dst = smb + (uint32_t)s * STAGE_BYTES;
            const float* a = Ablk + (c + 3) * 16;
            const float* w = Wblk + (c + 3) * 16;
#pragma unroll
            for (int it = 0; it < 4; it++) {
                const int row = it * 32 + ld_r;
                const uint32_t so = dst + (uint32_t)((row * SST + ld_f) * 4);
                CP_ASYNC16(so, a + (size_t)row * DM + ld_f);
                CP_ASYNC16(so + 2560 * 4, w + (size_t)row * DM + ld_f);
            }
        }
        CP_COMMIT();

        const uint32_t asb = smb + (uint32_t)(c & 3) * STAGE_BYTES;
        const uint32_t wsb = asb + 2560 * 4;
#pragma unroll
        for (int k0 = 0; k0 < 16; k0 += 8) {
            uint32_t af[4][4], bf[4][4];
#pragma unroll
            for (int mt = 0; mt < 4; mt++)
                LDSM_X4(af[mt], asb + (uint32_t)(((a_row + mt * 16) * SST + k0 + a_col) * 4));
#pragma unroll
            for (int p = 0; p < 4; p++)
                LDSM_X4(bf[p], wsb + (uint32_t)(((b_row + p * 16) * SST + k0 + b_col) * 4));
            // convert raw f32 fragments -> tf32 (same numerics as pre-convert)
#pragma unroll
            for (int mt = 0; mt < 4; mt++)
#pragma unroll
                for (int e = 0; e < 4; e++)
                    af[mt][e] = f2tf32(__uint_as_float(af[mt][e]));
#pragma unroll
            for (int p = 0; p < 4; p++)
#pragma unroll
                for (int e = 0; e < 4; e++)
                    bf[p][e] = f2tf32(__uint_as_float(bf[p][e]));
#pragma unroll
            for (int nt = 0; nt < 8; nt++) {
                const uint32_t b0 = bf[nt >> 1][(nt & 1) << 1];
                const uint32_t b1 = bf[nt >> 1][((nt & 1) << 1) + 1];
#pragma unroll
                for (int mt = 0; mt < 4; mt++)
                    MMA_TF32(acc[mt][nt], af[mt], b0, b1);
            }
        }
    }
}

__global__ void __launch_bounds__(128) qkv_gemm_mma(const float* __restrict__ Xq,
                                                    const float* __restrict__ Xkv,
                                                    const float* __restrict__ Wq,
                                                    const float* __restrict__ Wk,
                                                    const float* __restrict__ Wv) {
    extern __shared__ uint32_t smg[];
    const int bz = blockIdx.z;
    const float* A = (bz == 0) ? Xq : Xkv;
    const float* W = (bz == 0) ? Wq : ((bz == 1) ? Wk : Wv);
    float* out     = (bz == 0) ? g_Q : ((bz == 1) ? g_K : g_V);
    const float scale = (bz == 0) ? 0.125f : 1.0f;

    const int m0 = blockIdx.y * 128;
    const int n0 = blockIdx.x * 128;
    const int tid = threadIdx.x;
    const int lane = tid & 31, wid = tid >> 5;
    const int wm = (wid & 1) << 6, wn = (wid >> 1) << 6;
    const int r = lane >> 2, cl = lane & 3;

    float acc[4][8][4];
    gemm_mainloop_cp(A + (size_t)m0 * DM, W + (size_t)n0 * DM, smg, acc, tid);

#pragma unroll
    for (int mt = 0; mt < 4; mt++) {
#pragma unroll
        for (int nt = 0; nt < 8; nt++) {
            const int mr = m0 + wm + mt * 16 + r;
            const int nc = n0 + wn + nt * 8 + 2 * cl;
            const int b = mr >> 11, s = mr & 2047;
            const int h = nc >> 6, dh = nc & 63;
            float* p0 = out + (((size_t)(b * NH + h) * SEQ + s) * DH + dh);
            *(float2*)p0 = make_float2(acc[mt][nt][0] * scale, acc[mt][nt][1] * scale);
            float* p1 = out + (((size_t)(b * NH + h) * SEQ + (s + 8)) * DH + dh);
            *(float2*)p1 = make_float2(acc[mt][nt][2] * scale, acc[mt][nt][3] * scale);
        }
    }
}

__global__ void __launch_bounds__(128) proj_gemm_mma(const float* __restrict__ Wo,
                                                     float* __restrict__ C) {
    extern __shared__ uint32_t smg[];
    const int m0 = blockIdx.y * 128;
    const int n0 = blockIdx.x * 128;
    const int tid = threadIdx.x;
    const int lane = tid & 31, wid = tid >> 5;
    const int wm = (wid & 1) << 6, wn = (wid >> 1) << 6;
    const int r = lane >> 2, cl = lane & 3;

    float acc[4][8][4];
    gemm_mainloop_cp(g_O + (size_t)m0 * DM, Wo + (size_t)n0 * DM, smg, acc, tid);

#pragma unroll
    for (int mt = 0; mt < 4; mt++) {
#pragma unroll
        for (int nt = 0; nt < 8; nt++) {
            const int mr = m0 + wm + mt * 16 + r;
            const int nc = n0 + wn + nt * 8 + 2 * cl;
            *(float2*)&C[(size_t)mr * DM + nc] = make_float2(acc[mt][nt][0], acc[mt][nt][1]);
            *(float2*)&C[(size_t)(mr + 8) * DM + nc] = make_float2(acc[mt][nt][2], acc[mt][nt][3]);
        }
    }
}

// ============================================================================
// Flash attention with tf32 mma.sync + ldmatrix fragments (unchanged, R5).
// BQ=128, BK=64, Dh=64, 256 threads (8 warps x 16 q-rows each).
// ============================================================================
#define AST 68
#define OFF_Q 0
#define OFF_K (128 * AST)
#define OFF_V (192 * AST)
#define OFF_P (256 * AST)
#define ATTN_SMEM_BYTES (384 * AST * 4)

__global__ void __launch_bounds__(256) attn_mma() {
    extern __shared__ uint32_t sm4[];
    uint32_t* Qs = sm4 + OFF_Q;
    uint32_t* Ks = sm4 + OFF_K;
    uint32_t* Vs = sm4 + OFF_V;
    uint32_t* Ps = sm4 + OFF_P;

    const int tid = threadIdx.x;
    const int wid = tid >> 5, lane = tid & 31;
    const int r = lane >> 2, cl = lane & 3;
    const int mat = lane >> 3, lrow = lane & 7;
    const int qt = (int)(gridDim.x - 1) - (int)blockIdx.x;   // heavy first
    const int bh = blockIdx.y;
    const int q0 = qt * 128;
    const int wq = wid * 16;
    const size_t base = (size_t)bh * SEQ * DH;

    const uint32_t Qs_b = smem_u32(Qs), Ks_b = smem_u32(Ks);
    const uint32_t Vs_b = smem_u32(Vs), Ps_b = smem_u32(Ps);
    const int a_off = ((mat & 1) << 3) + lrow;
    const int a_col = (mat >> 1) << 2;
    const int b_off = ((mat >> 1) << 3) + lrow;
    const int b_col = (mat & 1) << 2;

#pragma unroll
    for (int it = 0; it < 8; it++) {
        const int id = it * 256 + tid;
        const int row = id >> 4, f4 = (id & 15) << 2;
        float4 v = *(const float4*)&g_Q[base + (size_t)(q0 + row) * DH + f4];
        uint4 t = make_uint4(f2tf32(v.x), f2tf32(v.y), f2tf32(v.z), f2tf32(v.w));
        *(uint4*)&Qs[row * AST + f4] = t;
    }

    float o[8][4];
#pragma unroll
    for (int nf = 0; nf < 8; nf++)
#pragma unroll
        for (int e = 0; e < 4; e++) o[nf][e] = 0.0f;
    float m0v = -1e30f, m1v = -1e30f, l0v = 0.0f, l1v = 0.0f;

    const int vc = tid & 63;
    const int vdg = (tid >> 6) << 4;

    const int ntiles = 2 * qt + 2;
    for (int t = 0; t < ntiles; t++) {
        const int k0g = t * 64;
        __syncthreads();
#pragma unroll
        for (int it = 0; it < 4; it++) {
            const int id = it * 256 + tid;
            const int c = id >> 4, f4 = (id & 15) << 2;
            float4 v = *(const float4*)&g_K[base + (size_t)(k0g + c) * DH + f4];
            uint4 tt = make_uint4(f2tf32(v.x), f2tf32(v.y), f2tf32(v.z), f2tf32(v.w));
            *(uint4*)&Ks[c * AST + f4] = tt;
        }
#pragma unroll
        for (int i = 0; i < 4; i++) {
            float4 v = *(const float4*)&g_V[base + (size_t)(k0g + vc) * DH + vdg + i * 4];
            Vs[(vdg + i * 4 + 0) * AST + vc] = f2tf32(v.x);
            Vs[(vdg + i * 4 + 1) * AST + vc] = f2tf32(v.y);
            Vs[(vdg + i * 4 + 2) * AST + vc] = f2tf32(v.z);
            Vs[(vdg + i * 4 + 3) * AST + vc] = f2tf32(v.w);
        }
        __syncthreads();

        float sfr[8][4];
#pragma unroll
        for (int nf = 0; nf < 8; nf++)
#pragma unroll
            for (int e = 0; e < 4; e++) sfr[nf][e] = 0.0f;
#pragma unroll
        for (int k = 0; k < 8; k++) {
            const int k0 = k * 8;
            uint32_t af[4], bf[4][4];
            LDSM_X4(af, Qs_b + (uint32_t)(((wq + a_off) * AST + k0 + a_col) * 4));
#pragma unroll
            for (int p = 0; p < 4; p++)
                LDSM_X4(bf[p], Ks_b + (uint32_t)(((p * 16 + b_off) * AST + k0 + b_col) * 4));
#pragma unroll
            for (int nf = 0; nf < 8; nf++)
                MMA_TF32(sfr[nf], af, bf[nf >> 1][(nf & 1) << 1], bf[nf >> 1][((nf & 1) << 1) + 1]);
        }

        if (t >= 2 * qt) {
            const int row0 = q0 + wq + r, row1 = row0 + 8;
#pragma unroll
            for (int nf = 0; nf < 8; nf++) {
                const int c0 = k0g + nf * 8 + 2 * cl;
                if (c0 > row0) sfr[nf][0] = -1e30f;
                if (c0 + 1 > row0) sfr[nf][1] = -1e30f;
                if (c0 > row1) sfr[nf][2] = -1e30f;
                if (c0 + 1 > row1) sfr[nf][3] = -1e30f;
            }
        }

        float mx0 = -1e30f, mx1 = -1e30f;
#pragma unroll
        for (int nf = 0; nf < 8; nf++) {
            mx0 = fmaxf(mx0, fmaxf(sfr[nf][0], sfr[nf][1]));
            mx1 = fmaxf(mx1, fmaxf(sfr[nf][2], sfr[nf][3]));
        }
        mx0 = fmaxf(mx0, __shfl_xor_sync(0xffffffffu, mx0, 1));
        mx0 = fmaxf(mx0, __shfl_xor_sync(0xffffffffu, mx0, 2));
        mx1 = fmaxf(mx1, __shfl_xor_sync(0xffffffffu, mx1, 1));
        mx1 = fmaxf(mx1, __shfl_xor_sync(0xffffffffu, mx1, 2));
        const float mn0 = fmaxf(m0v, mx0), mn1 = fmaxf(m1v, mx1);
        const float a0 = __expf(m0v - mn0), a1 = __expf(m1v - mn1);
        float rs0 = 0.0f, rs1 = 0.0f;
        uint32_t* pb0 = Ps + (wq + r) * AST + 2 * cl;
        uint32_t* pb1 = pb0 + 8 * AST;
#pragma unroll
        for (int nf = 0; nf < 8; nf++) {
            const float p0 = __expf(sfr[nf][0] - mn0);
            const float p1 = __expf(sfr[nf][1] - mn0);
            const float p2 = __expf(sfr[nf][2] - mn1);
            const float p3 = __expf(sfr[nf][3] - mn1);
            rs0 += p0 + p1;
            rs1 += p2 + p3;
            pb0[nf * 8 + 0] = f2tf32(p0);
            pb0[nf * 8 + 1] = f2tf32(p1);
            pb1[nf * 8 + 0] = f2tf32(p2);
            pb1[nf * 8 + 1] = f2tf32(p3);
        }
        rs0 += __shfl_xor_sync(0xffffffffu, rs0, 1);
        rs0 += __shfl_xor_sync(0xffffffffu, rs0, 2);
        rs1 += __shfl_xor_sync(0xffffffffu, rs1, 1);
        rs1 += __shfl_xor_sync(0xffffffffu, rs1, 2);
        l0v = l0v * a0 + rs0;
        l1v = l1v * a1 + rs1;
        m0v = mn0;
        m1v = mn1;
#pragma unroll
        for (int nf = 0; nf < 8; nf++) {
            o[nf][0] *= a0;
            o[nf][1] *= a0;
            o[nf][2] *= a1;
            o[nf][3] *= a1;
        }
        __syncwarp();

#pragma unroll
        for (int k = 0; k < 8; k++) {
            const int k0 = k * 8;
            uint32_t af[4], bf[4][4];
            LDSM_X4(af, Ps_b + (uint32_t)(((wq + a_off) * AST + k0 + a_col) * 4));
#pragma unroll
            for (int p = 0; p < 4; p++)
                LDSM_X4(bf[p], Vs_b + (uint32_t)(((p * 16 + b_off) * AST + k0 + b_col) * 4));
#pragma unroll
            for (int nf = 0; nf < 8; nf++)
                MMA_TF32(o[nf], af, bf[nf >> 1][(nf & 1) << 1], bf[nf >> 1][((nf & 1) << 1) + 1]);
        }
    }

    const float i0 = 1.0f / l0v, i1 = 1.0f / l1v;
    const int b = bh >> 4, h = bh & 15;
    const int row0 = q0 + wq + r, row1 = row0 + 8;
#pragma unroll
    for (int nf = 0; nf < 8; nf++) {
        const int col = h * DH + nf * 8 + 2 * cl;
        *(float2*)&g_O[(size_t)(b * SEQ + row0) * DM + col] =
            make_float2(o[nf][0] * i0, o[nf][1] * i0);
        *(float2*)&g_O[(size_t)(b * SEQ + row1) * DM + col] =
            make_float2(o[nf][2] * i1, o[nf][3] * i1);
    }
}

// ============================================================================
// Launch
// ============================================================================
extern "C" void kernel_launch(void* const* d_in, const int* in_sizes, int n_in,
                              void* d_out, int out_size) {
    const float* q  = (const float*)d_in[0];
    const float* kv = (const float*)d_in[1];
    const float* Wq = (const float*)d_in[2];
    const float* Wk = (const float*)d_in[3];
    const float* Wv = (const float*)d_in[4];
    const float* Wo = (const float*)d_in[5];
    float* out = (float*)d_out;

    cudaFuncSetAttribute(qkv_gemm_mma, cudaFuncAttributeMaxDynamicSharedMemorySize,
                         GEMM_SMEM_BYTES);
    cudaFuncSetAttribute(proj_gemm_mma, cudaFuncAttributeMaxDynamicSharedMemorySize,
                         GEMM_SMEM_BYTES);
    cudaFuncSetAttribute(attn_mma, cudaFuncAttributeMaxDynamicSharedMemorySize,
                         ATTN_SMEM_BYTES);

    qkv_gemm_mma<<<dim3(DM / 128, (BATCH * SEQ) / 128, 3), 128, GEMM_SMEM_BYTES>>>(q, kv, Wq, Wk, Wv);
    attn_mma<<<dim3(SEQ / 128, BATCH * NH), 256, ATTN_SMEM_BYTES>>>();
    proj_gemm_mma<<<dim3(DM / 128, (BATCH * SEQ) / 128), 128, GEMM_SMEM_BYTES>>>(Wo, out);
}